// round 15
// baseline (speedup 1.0000x reference)
#include <cuda_runtime.h>
#include <cstdint>

#define NNODES 50000
#define OUTD   128

// ---------------- device scratch (no allocations allowed) ----------------
// Zero-initialized at module load. INVARIANT: g_S4 and g_cnt are all-zero at
// entry of every kernel_launch call; final_kernel restores the zeros it
// consumes, so the invariant holds across graph replays. No zero_kernel.
__device__ float4 g_S4[NNODES * (OUTD / 4)];   // 25.6 MB accumulator S[N][128]
__device__ float  g_cnt[NNODES];               // per-node edge count (as float)
__device__ float4 g_Wp4[OUTD * OUTD / 4];      // Wc k-paired [k2][o][2]
__device__ float  g_bc[OUTD];                  // W2 @ b1

// ---------------- f32x2 helpers ------------------------------------------
__device__ __forceinline__ void unpack2(unsigned long long v, float& x, float& y) {
    asm("mov.b64 {%0, %1}, %2;" : "=f"(x), "=f"(y) : "l"(v));
}
__device__ __forceinline__ void ffma2(unsigned long long& d,
                                      unsigned long long a,
                                      unsigned long long b) {
    asm("fma.rn.f32x2 %0, %1, %2, %0;" : "+l"(d) : "l"(a), "l"(b));
}
__device__ __forceinline__ void red4(float* dst, float4 v) {
    asm volatile("red.global.add.v4.f32 [%0], {%1, %2, %3, %4};"
                 :: "l"(dst), "f"(v.x), "f"(v.y), "f"(v.z), "f"(v.w)
                 : "memory");
}

// ---------------- prep: Wc = W2@W1 (k-paired) + bc = W2@b1 ---------------
// One block per o, 128 threads. W2 row STAGED IN SMEM (the R14 profile showed
// 512 broadcast global loads per block made this kernel a 36.8us hog).
__global__ void __launch_bounds__(128) prep_kernel(const float* __restrict__ W1,
                                                   const float* __restrict__ W2,
                                                   const float* __restrict__ b1) {
    __shared__ float sw2[512];
    __shared__ float sb[128];
    const int o = blockIdx.x;
    const int k = threadIdx.x;

    // stage w2row coalesced: 4 loads per thread
    #pragma unroll
    for (int j = 0; j < 4; ++j)
        sw2[k + 128 * j] = __ldg(&W2[(size_t)o * 512 + k + 128 * j]);
    __syncthreads();

    sb[k] = sw2[k] * __ldg(&b1[k])
          + sw2[k + 128] * __ldg(&b1[k + 128])
          + sw2[k + 256] * __ldg(&b1[k + 256])
          + sw2[k + 384] * __ldg(&b1[k + 384]);

    float acc = 0.f;
    #pragma unroll 8
    for (int h = 0; h < 512; ++h)
        acc += sw2[h] * __ldg(&W1[(size_t)h * OUTD + k]);
    // k-paired store: float index (k/2)*256 + o*2 + (k&1)
    ((float*)g_Wp4)[(k >> 1) * 256 + o * 2 + (k & 1)] = acc;

    __syncthreads();
    if (k < 32) {
        float s = sb[k] + sb[k + 32] + sb[k + 64] + sb[k + 96];
        #pragma unroll
        for (int d = 16; d > 0; d >>= 1)
            s += __shfl_down_sync(0xffffffffu, s, d);
        if (k == 0) g_bc[o] = s;
    }
}

// ---------------- scatter: S[index[e]] += msg[e]; cnt += 1 ---------------
// Warp per edge; DRAM/LTS bound; 94.6-95.4us across 7 runs. Verbatim.
__global__ void scatter_kernel(const float4* __restrict__ msg4,
                               const int* __restrict__ index, int E) {
    int lane  = threadIdx.x & 31;
    int warp  = (blockIdx.x * blockDim.x + threadIdx.x) >> 5;
    int nwarp = (gridDim.x * blockDim.x) >> 5;

    int e = warp;
    for (; e + 3 * nwarp < E; e += 4 * nwarp) {
        int e0 = e, e1 = e + nwarp, e2 = e + 2 * nwarp, e3 = e + 3 * nwarp;
        int n0 = __ldg(index + e0);
        int n1 = __ldg(index + e1);
        int n2 = __ldg(index + e2);
        int n3 = __ldg(index + e3);
        float4 v0 = __ldg(msg4 + (size_t)e0 * 32 + lane);
        float4 v1 = __ldg(msg4 + (size_t)e1 * 32 + lane);
        float4 v2 = __ldg(msg4 + (size_t)e2 * 32 + lane);
        float4 v3 = __ldg(msg4 + (size_t)e3 * 32 + lane);
        red4((float*)&g_S4[(size_t)n0 * 32 + lane], v0);
        red4((float*)&g_S4[(size_t)n1 * 32 + lane], v1);
        red4((float*)&g_S4[(size_t)n2 * 32 + lane], v2);
        red4((float*)&g_S4[(size_t)n3 * 32 + lane], v3);
        if (lane == 0) {
            atomicAdd(&g_cnt[n0], 1.0f);
            atomicAdd(&g_cnt[n1], 1.0f);
            atomicAdd(&g_cnt[n2], 1.0f);
            atomicAdd(&g_cnt[n3], 1.0f);
        }
    }
    for (; e < E; e += nwarp) {
        int n = __ldg(index + e);
        float4 v = __ldg(msg4 + (size_t)e * 32 + lane);
        red4((float*)&g_S4[(size_t)n * 32 + lane], v);
        if (lane == 0) atomicAdd(&g_cnt[n], 1.0f);
    }
}

// ---------------- final: out = leaky(S @ WcT + cnt*bc + b2) --------------
// Same GEMM as R13/R14 (best measured) PLUS zero-restoration of g_S4/g_cnt:
// each block zeroes exactly the S rows / cnt entries it consumed, after
// reading them (in-thread WAR order; kc=1's leading barrier orders the
// cnt zeroing after all in-block cnt reads).
__global__ void __launch_bounds__(256, 2) final_kernel(const float* __restrict__ b2,
                                                       float* __restrict__ out, int N) {
    __shared__ __align__(16) float sS[64 * 64];   // 16384 B
    __shared__ float4 sW[32 * 64];                // 32768 B (total 49152 B)

    const int t    = threadIdx.x;
    const int tx   = t & 15;           // col group: cols 8tx .. 8tx+7
    const int ty   = t >> 4;           // row group: rows 4ty .. 4ty+3
    const int row0 = blockIdx.x * 64;

    // read edge counts BEFORE any zeroing (registers)
    float cntv[4];
    #pragma unroll
    for (int r = 0; r < 4; ++r) {
        int n = row0 + 4 * ty + r;
        cntv[r] = (n < N) ? g_cnt[n] : 0.f;
    }

    unsigned long long acc[4][8];
    #pragma unroll
    for (int r = 0; r < 4; ++r)
        #pragma unroll
        for (int j = 0; j < 8; ++j) acc[r][j] = 0ull;

    const float* sR0 = sS + (4 * ty + 0) * 64;
    const float* sR1 = sS + (4 * ty + 1) * 64;
    const float* sR2 = sS + (4 * ty + 2) * 64;
    const float* sR3 = sS + (4 * ty + 3) * 64;

    const float4 z4 = make_float4(0.f, 0.f, 0.f, 0.f);

    #pragma unroll 1
    for (int kc = 0; kc < 2; ++kc) {
        __syncthreads();               // prior chunk's reads done; for kc=1
                                       // also orders cnt reads before zeroing

        // fill sS (coalesced float4) and restore zeros in g_S4 behind us
        #pragma unroll
        for (int j = 0; j < 4; ++j) {
            int f = t + 256 * j;       // 0..1023
            int r = f >> 4;            // row 0..63
            int c4 = f & 15;           // float4 within k-chunk
            int n = row0 + r;
            float4 v = z4;
            if (n < N) {
                float4* gp = &g_S4[(size_t)n * 32 + kc * 16 + c4];
                v = __ldg(gp);
                *gp = z4;              // restore invariant (WAR, in-thread)
                if (kc == 1 && c4 == 0) g_cnt[n] = 0.f;  // after kc=1 barrier
            }
            *(float4*)&sS[r * 64 + 4 * c4] = v;
        }

        // fill sW: 8 float4 per thread, permuted store
        #pragma unroll
        for (int i = 0; i < 8; ++i) {
            int f = t + 256 * i;       // 0..2047
            int k2 = f >> 6;           // 0..31 (within chunk)
            int u  = f & 63;           // unit (k-pair x 2 cols)
            int pu = (u & 3) * 16 + (u >> 2);
            sW[k2 * 64 + pu] = g_Wp4[(size_t)(kc * 32 + k2) * 64 + u];
        }
        __syncthreads();

        #pragma unroll 2
        for (int k2 = 0; k2 < 32; k2 += 2) {
            float4 wa0 = sW[(k2 + 0) * 64 + 0 * 16 + tx];
            float4 wa1 = sW[(k2 + 0) * 64 + 1 * 16 + tx];
            float4 wa2 = sW[(k2 + 0) * 64 + 2 * 16 + tx];
            float4 wa3 = sW[(k2 + 0) * 64 + 3 * 16 + tx];
            float4 wb0 = sW[(k2 + 1) * 64 + 0 * 16 + tx];
            float4 wb1 = sW[(k2 + 1) * 64 + 1 * 16 + tx];
            float4 wb2 = sW[(k2 + 1) * 64 + 2 * 16 + tx];
            float4 wb3 = sW[(k2 + 1) * 64 + 3 * 16 + tx];
            float4 sv0 = *(const float4*)(sR0 + 2 * k2);
            float4 sv1 = *(const float4*)(sR1 + 2 * k2);
            float4 sv2 = *(const float4*)(sR2 + 2 * k2);
            float4 sv3 = *(const float4*)(sR3 + 2 * k2);

            const unsigned long long* qa0 = (const unsigned long long*)&wa0;
            const unsigned long long* qa1 = (const unsigned long long*)&wa1;
            const unsigned long long* qa2 = (const unsigned long long*)&wa2;
            const unsigned long long* qa3 = (const unsigned long long*)&wa3;
            const unsigned long long* qb0 = (const unsigned long long*)&wb0;
            const unsigned long long* qb1 = (const unsigned long long*)&wb1;
            const unsigned long long* qb2 = (const unsigned long long*)&wb2;
            const unsigned long long* qb3 = (const unsigned long long*)&wb3;

            #define ROW_STEP(r, sv)                                              \
            {                                                                    \
                const unsigned long long* sp = (const unsigned long long*)&(sv); \
                unsigned long long slo = sp[0], shi = sp[1];                     \
                ffma2(acc[r][0], slo, qa0[0]); ffma2(acc[r][1], slo, qa0[1]);    \
                ffma2(acc[r][2], slo, qa1[0]); ffma2(acc[r][3], slo, qa1[1]);    \
                ffma2(acc[r][4], slo, qa2[0]); ffma2(acc[r][5], slo, qa2[1]);    \
                ffma2(acc[r][6], slo, qa3[0]); ffma2(acc[r][7], slo, qa3[1]);    \
                ffma2(acc[r][0], shi, qb0[0]); ffma2(acc[r][1], shi, qb0[1]);    \
                ffma2(acc[r][2], shi, qb1[0]); ffma2(acc[r][3], shi, qb1[1]);    \
                ffma2(acc[r][4], shi, qb2[0]); ffma2(acc[r][5], shi, qb2[1]);    \
                ffma2(acc[r][6], shi, qb3[0]); ffma2(acc[r][7], shi, qb3[1]);    \
            }
            ROW_STEP(0, sv0)
            ROW_STEP(1, sv1)
            ROW_STEP(2, sv2)
            ROW_STEP(3, sv3)
            #undef ROW_STEP
        }
    }

    // ---- epilogue: cols 8tx..8tx+7 per row; fold k-pairs, bias, leaky ----
    const int c0 = 8 * tx;
    float bcv[8], b2v[8];
    #pragma unroll
    for (int j = 0; j < 8; ++j) {
        bcv[j] = g_bc[c0 + j];
        b2v[j] = __ldg(b2 + c0 + j);
    }
    #pragma unroll
    for (int r = 0; r < 4; ++r) {
        int n = row0 + 4 * ty + r;
        if (n >= N) continue;
        float res[8];
        #pragma unroll
        for (int j = 0; j < 8; ++j) {
            float lo, hi;
            unpack2(acc[r][j], lo, hi);
            float x = lo + hi + cntv[r] * bcv[j] + b2v[j];
            res[j] = (x >= 0.f) ? x : 0.01f * x;
        }
        float4* o4 = (float4*)(out + (size_t)n * OUTD + c0);
        o4[0] = make_float4(res[0], res[1], res[2], res[3]);
        o4[1] = make_float4(res[4], res[5], res[6], res[7]);
    }
}

// ---------------- launch: pure kernel launches, no API calls -------------
extern "C" void kernel_launch(void* const* d_in, const int* in_sizes, int n_in,
                              void* d_out, int out_size) {
    // metadata order: msg, x_i, x_j, e_ij, index, num_nodes, W1, b1, W2, b2
    const float* msg   = (const float*)d_in[0];
    const int*   index = (const int*)  d_in[4];
    const float* W1    = (const float*)d_in[6];
    const float* b1    = (const float*)d_in[7];
    const float* W2    = (const float*)d_in[8];
    const float* b2    = (const float*)d_in[9];
    float* out = (float*)d_out;

    int E = in_sizes[4];
    int N = out_size / OUTD;
    if (N > NNODES) N = NNODES;

    prep_kernel<<<OUTD, 128>>>(W1, W2, b1);
    scatter_kernel<<<12500, 256>>>((const float4*)msg, index, E);
    final_kernel<<<(N + 63) / 64, 256>>>(b2, out, N);
}

// round 17
// speedup vs baseline: 1.2006x; 1.2006x over previous
#include <cuda_runtime.h>
#include <cstdint>

#define NNODES 50000
#define OUTD   128

// ---------------- device scratch (no allocations allowed) ----------------
__device__ float4 g_S4[NNODES * (OUTD / 4)];   // 25.6 MB accumulator S[N][128]
__device__ float  g_cnt[NNODES];               // per-node edge count (as float)
__device__ float4 g_Wp4[OUTD * OUTD / 4];      // Wc k-paired [k2][o][2]
__device__ float  g_bc[OUTD];                  // W2 @ b1

// ---------------- f32x2 helpers ------------------------------------------
__device__ __forceinline__ void unpack2(unsigned long long v, float& x, float& y) {
    asm("mov.b64 {%0, %1}, %2;" : "=f"(x), "=f"(y) : "l"(v));
}
__device__ __forceinline__ void ffma2(unsigned long long& d,
                                      unsigned long long a,
                                      unsigned long long b) {
    asm("fma.rn.f32x2 %0, %1, %2, %0;" : "+l"(d) : "l"(a), "l"(b));
}
__device__ __forceinline__ void red4(float* dst, float4 v) {
    asm volatile("red.global.add.v4.f32 [%0], {%1, %2, %3, %4};"
                 :: "l"(dst), "f"(v.x), "f"(v.y), "f"(v.z), "f"(v.w)
                 : "memory");
}

// ------- merged prep + zero (256-thread blocks ONLY — R14-passing shape) --
// Blocks 0..127: prep for o = blockIdx.x.
//   Wc via k-VECTORIZED loads: thread (g = t>>5, lane = t&31) accumulates a
//   float4 of k = 4*lane..4*lane+3 over h in [64g, 64g+64). Coalesced
//   LDG.128, 8 independent h-groups -> high MLP (R15 showed thread-per-k
//   scalar loads gave MLP~2, 35us). Partials reduced in smem.
// Blocks 128..: grid-stride zero of g_S4 / g_cnt (overlaps prep).
__global__ void __launch_bounds__(256) prepzero_kernel(const float* __restrict__ W1,
                                                       const float* __restrict__ W2,
                                                       const float* __restrict__ b1) {
    if (blockIdx.x < 128) {
        __shared__ float  sw2[512];
        __shared__ float  sb[128];
        __shared__ float4 spart[256];  // 8 h-groups x 32 lanes
        const int o    = blockIdx.x;
        const int t    = threadIdx.x;
        const int g    = t >> 5;       // h-group 0..7
        const int lane = t & 31;       // k-float4 index

        // stage w2row: 2 coalesced loads per thread
        sw2[t]       = __ldg(&W2[(size_t)o * 512 + t]);
        sw2[t + 256] = __ldg(&W2[(size_t)o * 512 + t + 256]);
        __syncthreads();

        // bc partials (threads 0..127)
        if (t < 128) {
            sb[t] = sw2[t] * __ldg(&b1[t])
                  + sw2[t + 128] * __ldg(&b1[t + 128])
                  + sw2[t + 256] * __ldg(&b1[t + 256])
                  + sw2[t + 384] * __ldg(&b1[t + 384]);
        }

        // Wc partial: float4 over k, h in [64g, 64g+64), unroll 4
        {
            const float4* W14 = (const float4*)W1;   // [h][32] float4 rows
            const float*  w2g = sw2 + 64 * g;
            float4 a0 = make_float4(0.f, 0.f, 0.f, 0.f);
            float4 a1 = make_float4(0.f, 0.f, 0.f, 0.f);
            float4 a2 = make_float4(0.f, 0.f, 0.f, 0.f);
            float4 a3 = make_float4(0.f, 0.f, 0.f, 0.f);
            #pragma unroll 4
            for (int h = 0; h < 64; h += 4) {
                float4 v0 = __ldg(&W14[(size_t)(64 * g + h + 0) * 32 + lane]);
                float4 v1 = __ldg(&W14[(size_t)(64 * g + h + 1) * 32 + lane]);
                float4 v2 = __ldg(&W14[(size_t)(64 * g + h + 2) * 32 + lane]);
                float4 v3 = __ldg(&W14[(size_t)(64 * g + h + 3) * 32 + lane]);
                float c0 = w2g[h + 0], c1 = w2g[h + 1];
                float c2 = w2g[h + 2], c3 = w2g[h + 3];
                a0.x += c0 * v0.x; a0.y += c0 * v0.y; a0.z += c0 * v0.z; a0.w += c0 * v0.w;
                a1.x += c1 * v1.x; a1.y += c1 * v1.y; a1.z += c1 * v1.z; a1.w += c1 * v1.w;
                a2.x += c2 * v2.x; a2.y += c2 * v2.y; a2.z += c2 * v2.z; a2.w += c2 * v2.w;
                a3.x += c3 * v3.x; a3.y += c3 * v3.y; a3.z += c3 * v3.z; a3.w += c3 * v3.w;
            }
            a0.x += a1.x + a2.x + a3.x;
            a0.y += a1.y + a2.y + a3.y;
            a0.z += a1.z + a2.z + a3.z;
            a0.w += a1.w + a2.w + a3.w;
            spart[t] = a0;
        }
        __syncthreads();

        // fold 8 h-groups (threads 0..31), write k-paired
        if (t < 32) {
            float4 w = spart[t];
            #pragma unroll
            for (int gg = 1; gg < 8; ++gg) {
                float4 p = spart[gg * 32 + t];
                w.x += p.x; w.y += p.y; w.z += p.z; w.w += p.w;
            }
            int k0 = 4 * t;
            float* Wf = (float*)g_Wp4;
            Wf[((k0 + 0) >> 1) * 256 + o * 2 + ((k0 + 0) & 1)] = w.x;
            Wf[((k0 + 1) >> 1) * 256 + o * 2 + ((k0 + 1) & 1)] = w.y;
            Wf[((k0 + 2) >> 1) * 256 + o * 2 + ((k0 + 2) & 1)] = w.z;
            Wf[((k0 + 3) >> 1) * 256 + o * 2 + ((k0 + 3) & 1)] = w.w;
        }
        // bc reduce (threads 32..63 free; use 0..31 after above, cheap)
        if (t < 32) {
            float s = sb[t] + sb[t + 32] + sb[t + 64] + sb[t + 96];
            #pragma unroll
            for (int d = 16; d > 0; d >>= 1)
                s += __shfl_down_sync(0xffffffffu, s, d);
            if (t == 0) g_bc[o] = s;
        }
    } else {
        int i = (blockIdx.x - 128) * blockDim.x + threadIdx.x;
        int stride = (gridDim.x - 128) * blockDim.x;
        const int n4 = NNODES * (OUTD / 4);
        for (int j = i; j < n4; j += stride)
            g_S4[j] = make_float4(0.f, 0.f, 0.f, 0.f);
        for (int j = i; j < NNODES; j += stride) g_cnt[j] = 0.f;
    }
}

// ---------------- scatter: S[index[e]] += msg[e]; cnt += 1 ---------------
// Warp per edge; DRAM/LTS bound; 94.6-95.4us across 7 runs. Verbatim.
__global__ void scatter_kernel(const float4* __restrict__ msg4,
                               const int* __restrict__ index, int E) {
    int lane  = threadIdx.x & 31;
    int warp  = (blockIdx.x * blockDim.x + threadIdx.x) >> 5;
    int nwarp = (gridDim.x * blockDim.x) >> 5;

    int e = warp;
    for (; e + 3 * nwarp < E; e += 4 * nwarp) {
        int e0 = e, e1 = e + nwarp, e2 = e + 2 * nwarp, e3 = e + 3 * nwarp;
        int n0 = __ldg(index + e0);
        int n1 = __ldg(index + e1);
        int n2 = __ldg(index + e2);
        int n3 = __ldg(index + e3);
        float4 v0 = __ldg(msg4 + (size_t)e0 * 32 + lane);
        float4 v1 = __ldg(msg4 + (size_t)e1 * 32 + lane);
        float4 v2 = __ldg(msg4 + (size_t)e2 * 32 + lane);
        float4 v3 = __ldg(msg4 + (size_t)e3 * 32 + lane);
        red4((float*)&g_S4[(size_t)n0 * 32 + lane], v0);
        red4((float*)&g_S4[(size_t)n1 * 32 + lane], v1);
        red4((float*)&g_S4[(size_t)n2 * 32 + lane], v2);
        red4((float*)&g_S4[(size_t)n3 * 32 + lane], v3);
        if (lane == 0) {
            atomicAdd(&g_cnt[n0], 1.0f);
            atomicAdd(&g_cnt[n1], 1.0f);
            atomicAdd(&g_cnt[n2], 1.0f);
            atomicAdd(&g_cnt[n3], 1.0f);
        }
    }
    for (; e < E; e += nwarp) {
        int n = __ldg(index + e);
        float4 v = __ldg(msg4 + (size_t)e * 32 + lane);
        red4((float*)&g_S4[(size_t)n * 32 + lane], v);
        if (lane == 0) atomicAdd(&g_cnt[n], 1.0f);
    }
}

// ---------------- final: out = leaky(S @ WcT + cnt*bc + b2) --------------
// R13/R14 version verbatim (best measured: 61.5us).
__global__ void __launch_bounds__(256, 2) final_kernel(const float* __restrict__ b2,
                                                       float* __restrict__ out, int N) {
    __shared__ __align__(16) float sS[64 * 64];   // 16384 B
    __shared__ float4 sW[32 * 64];                // 32768 B (total 49152 B)

    const int t    = threadIdx.x;
    const int tx   = t & 15;
    const int ty   = t >> 4;
    const int row0 = blockIdx.x * 64;

    unsigned long long acc[4][8];
    #pragma unroll
    for (int r = 0; r < 4; ++r)
        #pragma unroll
        for (int j = 0; j < 8; ++j) acc[r][j] = 0ull;

    const float* sR0 = sS + (4 * ty + 0) * 64;
    const float* sR1 = sS + (4 * ty + 1) * 64;
    const float* sR2 = sS + (4 * ty + 2) * 64;
    const float* sR3 = sS + (4 * ty + 3) * 64;

    #pragma unroll 1
    for (int kc = 0; kc < 2; ++kc) {
        __syncthreads();

        #pragma unroll
        for (int j = 0; j < 4; ++j) {
            int f = t + 256 * j;
            int r = f >> 4;
            int c4 = f & 15;
            int n = row0 + r;
            float4 v = make_float4(0.f, 0.f, 0.f, 0.f);
            if (n < N) v = __ldg(&g_S4[(size_t)n * 32 + kc * 16 + c4]);
            *(float4*)&sS[r * 64 + 4 * c4] = v;
        }

        #pragma unroll
        for (int i = 0; i < 8; ++i) {
            int f = t + 256 * i;
            int k2 = f >> 6;
            int u  = f & 63;
            int pu = (u & 3) * 16 + (u >> 2);
            sW[k2 * 64 + pu] = g_Wp4[(size_t)(kc * 32 + k2) * 64 + u];
        }
        __syncthreads();

        #pragma unroll 2
        for (int k2 = 0; k2 < 32; k2 += 2) {
            float4 wa0 = sW[(k2 + 0) * 64 + 0 * 16 + tx];
            float4 wa1 = sW[(k2 + 0) * 64 + 1 * 16 + tx];
            float4 wa2 = sW[(k2 + 0) * 64 + 2 * 16 + tx];
            float4 wa3 = sW[(k2 + 0) * 64 + 3 * 16 + tx];
            float4 wb0 = sW[(k2 + 1) * 64 + 0 * 16 + tx];
            float4 wb1 = sW[(k2 + 1) * 64 + 1 * 16 + tx];
            float4 wb2 = sW[(k2 + 1) * 64 + 2 * 16 + tx];
            float4 wb3 = sW[(k2 + 1) * 64 + 3 * 16 + tx];
            float4 sv0 = *(const float4*)(sR0 + 2 * k2);
            float4 sv1 = *(const float4*)(sR1 + 2 * k2);
            float4 sv2 = *(const float4*)(sR2 + 2 * k2);
            float4 sv3 = *(const float4*)(sR3 + 2 * k2);

            const unsigned long long* qa0 = (const unsigned long long*)&wa0;
            const unsigned long long* qa1 = (const unsigned long long*)&wa1;
            const unsigned long long* qa2 = (const unsigned long long*)&wa2;
            const unsigned long long* qa3 = (const unsigned long long*)&wa3;
            const unsigned long long* qb0 = (const unsigned long long*)&wb0;
            const unsigned long long* qb1 = (const unsigned long long*)&wb1;
            const unsigned long long* qb2 = (const unsigned long long*)&wb2;
            const unsigned long long* qb3 = (const unsigned long long*)&wb3;

            #define ROW_STEP(r, sv)                                              \
            {                                                                    \
                const unsigned long long* sp = (const unsigned long long*)&(sv); \
                unsigned long long slo = sp[0], shi = sp[1];                     \
                ffma2(acc[r][0], slo, qa0[0]); ffma2(acc[r][1], slo, qa0[1]);    \
                ffma2(acc[r][2], slo, qa1[0]); ffma2(acc[r][3], slo, qa1[1]);    \
                ffma2(acc[r][4], slo, qa2[0]); ffma2(acc[r][5], slo, qa2[1]);    \
                ffma2(acc[r][6], slo, qa3[0]); ffma2(acc[r][7], slo, qa3[1]);    \
                ffma2(acc[r][0], shi, qb0[0]); ffma2(acc[r][1], shi, qb0[1]);    \
                ffma2(acc[r][2], shi, qb1[0]); ffma2(acc[r][3], shi, qb1[1]);    \
                ffma2(acc[r][4], shi, qb2[0]); ffma2(acc[r][5], shi, qb2[1]);    \
                ffma2(acc[r][6], shi, qb3[0]); ffma2(acc[r][7], shi, qb3[1]);    \
            }
            ROW_STEP(0, sv0)
            ROW_STEP(1, sv1)
            ROW_STEP(2, sv2)
            ROW_STEP(3, sv3)
            #undef ROW_STEP
        }
    }

    const int c0 = 8 * tx;
    float bcv[8], b2v[8];
    #pragma unroll
    for (int j = 0; j < 8; ++j) {
        bcv[j] = g_bc[c0 + j];
        b2v[j] = __ldg(b2 + c0 + j);
    }
    #pragma unroll
    for (int r = 0; r < 4; ++r) {
        int n = row0 + 4 * ty + r;
        if (n >= N) continue;
        float cnt = g_cnt[n];
        float res[8];
        #pragma unroll
        for (int j = 0; j < 8; ++j) {
            float lo, hi;
            unpack2(acc[r][j], lo, hi);
            float x = lo + hi + cnt * bcv[j] + b2v[j];
            res[j] = (x >= 0.f) ? x : 0.01f * x;
        }
        float4* o4 = (float4*)(out + (size_t)n * OUTD + c0);
        o4[0] = make_float4(res[0], res[1], res[2], res[3]);
        o4[1] = make_float4(res[4], res[5], res[6], res[7]);
    }
}

// ---------------- launch: pure kernel launches, no API calls -------------
extern "C" void kernel_launch(void* const* d_in, const int* in_sizes, int n_in,
                              void* d_out, int out_size) {
    // metadata order: msg, x_i, x_j, e_ij, index, num_nodes, W1, b1, W2, b2
    const float* msg   = (const float*)d_in[0];
    const int*   index = (const int*)  d_in[4];
    const float* W1    = (const float*)d_in[6];
    const float* b1    = (const float*)d_in[7];
    const float* W2    = (const float*)d_in[8];
    const float* b2    = (const float*)d_in[9];
    float* out = (float*)d_out;

    int E = in_sizes[4];
    int N = out_size / OUTD;
    if (N > NNODES) N = NNODES;

    prepzero_kernel<<<128 + 2048, 256>>>(W1, W2, b1);
    scatter_kernel<<<12500, 256>>>((const float4*)msg, index, E);
    final_kernel<<<(N + 63) / 64, 256>>>(b2, out, N);
}